// round 11
// baseline (speedup 1.0000x reference)
#include <cuda_runtime.h>

// Shapes
// theta0: (256, 1024, 256)  idx = x0*262144 + j*256 + c
// theta1: (256, 256, 512)   idx = a*131072 + c*512 + j
// theta2: (256, 256, 512)   idx = c*131072 + b*512 + k
#define N0  67108864
#define N1  33554432
#define N2  33554432

// Scratch (device globals; fully rewritten every call -> deterministic)
__device__ float d_s0a[1024 * 256];      // sum over x0 of theta0  [j][c]
__device__ float d_S0p[2 * 256 * 512];   // partial sum over a of theta1 [half][c][j]
__device__ float d_S2[256 * 256];        // sum over j of theta1 [a][c]
__device__ float d_T2s[256 * 256];       // sum over k of theta2 [c][b]
__device__ float d_msg01[256 * 256];     // [a][c]
__device__ float d_msg12[256 * 256];     // [c][b]
__device__ float d_R[256 * 256];         // [c][b]  (msg21[c,j] = R[c, j>>1])
__device__ float d_Q[256 * 256];         // [a][c]  (msg10[j,c] = Q[j>>2, c])

// 256-bit evict_last load (sm_103a requires .v8.b32/.v4.b64 for this hint).
// Protects t1 lines in L2 across the KA2 -> KE boundary.
__device__ __forceinline__ void ldg_evict_last_8(const float* p, float* f) {
    unsigned long long a, b, c, d;
    asm volatile("ld.global.L2::evict_last.v4.b64 {%0,%1,%2,%3}, [%4];"
                 : "=l"(a), "=l"(b), "=l"(c), "=l"(d) : "l"(p));
    *(unsigned long long*)&f[0] = a;
    *(unsigned long long*)&f[2] = b;
    *(unsigned long long*)&f[4] = c;
    *(unsigned long long*)&f[6] = d;
}

// ---------------------------------------------------------------------------
// KA2: reduce t0 and t1. Block roles:
//   [0, 1024)     : k1  s0a[j][c] = sum_x0 theta0[x0,j,c]   (evict-first)
//   [1024, 1536)  : k2  dual reduction of theta1            (evict_LAST, grid tail)
__global__ void KA2_reduce(const float* __restrict__ t0,
                           const float* __restrict__ t1) {
    const unsigned bb = blockIdx.x;

    if (bb < 1024u) {
        // ---- k1 ----
        const int j = bb;
        const int c = threadIdx.x;
        const float* p = t0 + j * 256 + c;
        float a0 = 0.f, a1 = 0.f, a2 = 0.f, a3 = 0.f;
        float a4 = 0.f, a5 = 0.f, a6 = 0.f, a7 = 0.f;
        #pragma unroll 2
        for (int x = 0; x < 256; x += 8) {
            a0 += __ldcs(p + (size_t)(x + 0) * 262144);
            a1 += __ldcs(p + (size_t)(x + 1) * 262144);
            a2 += __ldcs(p + (size_t)(x + 2) * 262144);
            a3 += __ldcs(p + (size_t)(x + 3) * 262144);
            a4 += __ldcs(p + (size_t)(x + 4) * 262144);
            a5 += __ldcs(p + (size_t)(x + 5) * 262144);
            a6 += __ldcs(p + (size_t)(x + 6) * 262144);
            a7 += __ldcs(p + (size_t)(x + 7) * 262144);
        }
        d_s0a[j * 256 + c] = ((a0 + a1) + (a2 + a3)) + ((a4 + a5) + (a6 + a7));
        return;
    }

    // ---- k2: dual reduction of theta1 (evict_last reads) ----
    const unsigned b2 = bb - 1024u;
    const int c    = b2 >> 1;
    const int half = b2 & 1;
    const int tid  = threadIdx.x;
    const int wid  = tid >> 5;
    const int lane = tid & 31;

    __shared__ float sS0[8][512];

    float acc[16];
    #pragma unroll
    for (int i = 0; i < 16; i++) acc[i] = 0.f;

    #pragma unroll 2
    for (int it = 0; it < 16; it++) {
        const int a = half * 128 + wid * 16 + it;
        const float* row = t1 + (size_t)a * 131072 + (size_t)c * 512;
        float rs = 0.f;
        #pragma unroll
        for (int g = 0; g < 2; g++) {
            float f[8];
            ldg_evict_last_8(row + (g * 32 + lane) * 8, f);
            #pragma unroll
            for (int e = 0; e < 8; e++) acc[g * 8 + e] += f[e];
            rs += ((f[0] + f[1]) + (f[2] + f[3])) + ((f[4] + f[5]) + (f[6] + f[7]));
        }
        #pragma unroll
        for (int off = 16; off > 0; off >>= 1)
            rs += __shfl_down_sync(0xffffffffu, rs, off);
        if (lane == 0) d_S2[a * 256 + c] = rs;
    }

    #pragma unroll
    for (int g = 0; g < 2; g++) {
        float4* dst = (float4*)&sS0[wid][(g * 32 + lane) * 8];
        dst[0] = make_float4(acc[g * 8 + 0], acc[g * 8 + 1], acc[g * 8 + 2], acc[g * 8 + 3]);
        dst[1] = make_float4(acc[g * 8 + 4], acc[g * 8 + 5], acc[g * 8 + 6], acc[g * 8 + 7]);
    }
    __syncthreads();

    float s0 = 0.f, s1 = 0.f;
    #pragma unroll
    for (int w = 0; w < 8; w++) {
        s0 += sS0[w][tid];
        s1 += sS0[w][tid + 256];
    }
    d_S0p[half * 131072 + c * 512 + tid]       = s0;
    d_S0p[half * 131072 + c * 512 + tid + 256] = s1;
}

// ---------------------------------------------------------------------------
// K4a: msg01, colsum, msg12 (depends only on t0/t1 sums). grid=256 (c), block=256.
__global__ void K4a_messages() {
    const int c    = blockIdx.x;
    const int t    = threadIdx.x;
    const int lane = t & 31;
    const int wid  = t >> 5;
    __shared__ float sw[8];
    __shared__ float sbc;

    const float v0  = d_s0a[(4 * t + 0) * 256 + c];
    const float v1  = d_s0a[(4 * t + 1) * 256 + c];
    const float v2  = d_s0a[(4 * t + 2) * 256 + c];
    const float v3  = d_s0a[(4 * t + 3) * 256 + c];
    const float2 p0 = *(const float2*)&d_S0p[c * 512 + 2 * t];
    const float2 p1 = *(const float2*)&d_S0p[131072 + c * 512 + 2 * t];

    const float m01 = (v0 + v1) + (v2 + v3);
    d_msg01[t * 256 + c] = m01;

    float r = m01;
    #pragma unroll
    for (int o = 16; o > 0; o >>= 1) r += __shfl_down_sync(0xffffffffu, r, o);
    if (lane == 0) sw[wid] = r;
    __syncthreads();
    if (t == 0) {
        float s = 0.f;
        #pragma unroll
        for (int w = 0; w < 8; w++) s += sw[w];
        sbc = s;
    }
    __syncthreads();
    const float colsum = sbc;

    const float m12 = (p0.x + p1.x + colsum) + (p0.y + p1.y + colsum);
    d_msg12[c * 256 + t] = m12;
}

// ---------------------------------------------------------------------------
// KC: single pass over theta2: out2 = t2 + msg12[c,b]; accumulate T2s row sums.
// 8192 blocks x 8 warps, one 512-float row per warp. Streaming (ldcs/stcs) so
// protected t1 lines in L2 are not displaced.
__global__ void KC_t2(const float* __restrict__ t2, float* __restrict__ out2) {
    const int r    = blockIdx.x * 8 + (threadIdx.x >> 5);   // r = c*256 + b
    const int lane = threadIdx.x & 31;
    const float m = d_msg12[r];
    const float4* row  = (const float4*)(t2  + (size_t)r * 512);
    float4*       orow = (float4*)      (out2 + (size_t)r * 512);
    float s = 0.f;
    #pragma unroll
    for (int ch = 0; ch < 4; ch++) {
        float4 v = __ldcs(row + ch * 32 + lane);
        s += (v.x + v.y) + (v.z + v.w);
        v.x += m; v.y += m; v.z += m; v.w += m;
        __stcs(orow + ch * 32 + lane, v);
    }
    #pragma unroll
    for (int off = 16; off > 0; off >>= 1)
        s += __shfl_down_sync(0xffffffffu, s, off);
    if (lane == 0) d_T2s[r] = s;
}

// ---------------------------------------------------------------------------
// K4b: R, S21, Q. grid=256 (c), block=256 (t).
__global__ void K4b_messages() {
    const int c    = blockIdx.x;
    const int t    = threadIdx.x;
    const int lane = t & 31;
    const int wid  = t >> 5;
    __shared__ float sw[8];
    __shared__ float sbc;

    const float t2s = d_T2s[c * 256 + t];
    const float m12 = d_msg12[c * 256 + t];
    const float s2  = d_S2[t * 256 + c];
    const float m01 = d_msg01[t * 256 + c];

    const float Rv = t2s + 511.f * m12;
    d_R[c * 256 + t] = Rv;

    float r = Rv;
    #pragma unroll
    for (int o = 16; o > 0; o >>= 1) r += __shfl_down_sync(0xffffffffu, r, o);
    if (lane == 0) sw[wid] = r;
    __syncthreads();
    if (t == 0) {
        float s = 0.f;
        #pragma unroll
        for (int w = 0; w < 8; w++) s += sw[w];
        sbc = 2.f * s;
    }
    __syncthreads();

    d_Q[t * 256 + c] = s2 + 511.f * m01 + sbc;
}

// ---------------------------------------------------------------------------
// KE: outputs for theta1 and theta0.
//   [0, 32768)      : theta1 + msg01[a,c] + R[c, j>>1]  -- FIRST, c-DESCENDING
//                     (KA2's k2 read t1 by ascending c; high-c lines freshest)
//   [32768, 98304)  : theta0 + Q[j>>2, c]
__global__ void KE_outputs(const float* __restrict__ t0,
                           const float* __restrict__ t1,
                           float* __restrict__ out) {
    const unsigned bb = blockIdx.x;

    if (bb < 32768u) {
        // c-pair descending, a minor
        const int cp = 127 - (int)(bb >> 8);
        const int a  = (int)(bb & 255u);
        const int idx4 = a * 32768 + cp * 256 + threadIdx.x;
        const int i = idx4 << 2;
        const int j = i & 511;
        const int c = (i >> 9) & 255;
        const float m = d_msg01[a * 256 + c];
        const float2 rr = *(const float2*)&d_R[c * 256 + (j >> 1)];
        float4 v = __ldcs((const float4*)t1 + idx4);   // mostly L2 hits; demote after
        v.x += m + rr.x; v.y += m + rr.x;
        v.z += m + rr.y; v.w += m + rr.y;
        __stcs((float4*)(out + N0) + idx4, v);
        return;
    }

    {
        const int idx4 = (bb - 32768u) * 256 + threadIdx.x;
        const int i = idx4 << 2;
        const int c = i & 255;
        const int j = (i >> 8) & 1023;
        float4 v = __ldcs((const float4*)t0 + idx4);
        float4 q = ((const float4*)d_Q)[((j >> 2) << 6) + (c >> 2)];
        v.x += q.x; v.y += q.y; v.z += q.z; v.w += q.w;
        __stcs((float4*)out + idx4, v);
    }
}

// ---------------------------------------------------------------------------
extern "C" void kernel_launch(void* const* d_in, const int* in_sizes, int n_in,
                              void* d_out, int out_size) {
    const float* t0 = (const float*)d_in[0];
    const float* t1 = (const float*)d_in[1];
    const float* t2 = (const float*)d_in[2];
    float* out = (float*)d_out;

    KA2_reduce<<<1536, 256>>>(t0, t1);
    K4a_messages<<<256, 256>>>();
    KC_t2<<<8192, 256>>>(t2, out + N0 + N1);
    K4b_messages<<<256, 256>>>();
    KE_outputs<<<98304, 256>>>(t0, t1, out);
}

// round 12
// speedup vs baseline: 1.0086x; 1.0086x over previous
#include <cuda_runtime.h>

// Shapes
// theta0: (256, 1024, 256)  idx = x0*262144 + j*256 + c
// theta1: (256, 256, 512)   idx = a*131072 + c*512 + j
// theta2: (256, 256, 512)   idx = c*131072 + b*512 + k
#define N0  67108864
#define N1  33554432
#define N2  33554432

// Scratch (device globals; fully rewritten every call -> deterministic)
__device__ float d_s0a[1024 * 256];      // sum over x0 of theta0  [j][c]
__device__ float d_S0p[2 * 256 * 512];   // partial sum over a of theta1 [half][c][j]
__device__ float d_S2[256 * 256];        // sum over j of theta1 [a][c]
__device__ float d_msg01[256 * 256];     // [a][c]
__device__ float d_msg12[256 * 256];     // [c][b]
__device__ float d_R[256 * 256];         // [c][b]  (msg21[c,j] = R[c, j>>1])
__device__ float d_Q[256 * 256];         // [a][c]  (msg10[j,c] = Q[j>>2, c])

// 256-bit evict_last load (sm_103a requires .v8.b32/.v4.b64 for this hint).
// Protects t1 lines in L2 across the KA2 -> KE boundary.
__device__ __forceinline__ void ldg_evict_last_8(const float* p, float* f) {
    unsigned long long a, b, c, d;
    asm volatile("ld.global.L2::evict_last.v4.b64 {%0,%1,%2,%3}, [%4];"
                 : "=l"(a), "=l"(b), "=l"(c), "=l"(d) : "l"(p));
    *(unsigned long long*)&f[0] = a;
    *(unsigned long long*)&f[2] = b;
    *(unsigned long long*)&f[4] = c;
    *(unsigned long long*)&f[6] = d;
}

// evict_first policy store (createpolicy + cache_hint path, sm_80+ documented):
// KC's 134 MB of output stores must NOT displace the protected t1 lines.
__device__ __forceinline__ void stg_evict_first(float4* p, float4 v,
                                                unsigned long long pol) {
    asm volatile("st.global.L2::cache_hint.v4.f32 [%0], {%1,%2,%3,%4}, %5;"
                 :: "l"(p), "f"(v.x), "f"(v.y), "f"(v.z), "f"(v.w), "l"(pol)
                 : "memory");
}

// ---------------------------------------------------------------------------
// KA2: reduce t0 and t1. Block roles:
//   [0, 1024)     : k1  s0a[j][c] = sum_x0 theta0[x0,j,c]   (evict-first)
//   [1024, 1536)  : k2  dual reduction of theta1            (evict_LAST, grid tail)
__global__ void KA2_reduce(const float* __restrict__ t0,
                           const float* __restrict__ t1) {
    const unsigned bb = blockIdx.x;

    if (bb < 1024u) {
        // ---- k1 ----
        const int j = bb;
        const int c = threadIdx.x;
        const float* p = t0 + j * 256 + c;
        float a0 = 0.f, a1 = 0.f, a2 = 0.f, a3 = 0.f;
        float a4 = 0.f, a5 = 0.f, a6 = 0.f, a7 = 0.f;
        #pragma unroll 2
        for (int x = 0; x < 256; x += 8) {
            a0 += __ldcs(p + (size_t)(x + 0) * 262144);
            a1 += __ldcs(p + (size_t)(x + 1) * 262144);
            a2 += __ldcs(p + (size_t)(x + 2) * 262144);
            a3 += __ldcs(p + (size_t)(x + 3) * 262144);
            a4 += __ldcs(p + (size_t)(x + 4) * 262144);
            a5 += __ldcs(p + (size_t)(x + 5) * 262144);
            a6 += __ldcs(p + (size_t)(x + 6) * 262144);
            a7 += __ldcs(p + (size_t)(x + 7) * 262144);
        }
        d_s0a[j * 256 + c] = ((a0 + a1) + (a2 + a3)) + ((a4 + a5) + (a6 + a7));
        return;
    }

    // ---- k2: dual reduction of theta1 (evict_last reads) ----
    const unsigned b2 = bb - 1024u;
    const int c    = b2 >> 1;
    const int half = b2 & 1;
    const int tid  = threadIdx.x;
    const int wid  = tid >> 5;
    const int lane = tid & 31;

    __shared__ float sS0[8][512];

    float acc[16];
    #pragma unroll
    for (int i = 0; i < 16; i++) acc[i] = 0.f;

    #pragma unroll 2
    for (int it = 0; it < 16; it++) {
        const int a = half * 128 + wid * 16 + it;
        const float* row = t1 + (size_t)a * 131072 + (size_t)c * 512;
        float rs = 0.f;
        #pragma unroll
        for (int g = 0; g < 2; g++) {
            float f[8];
            ldg_evict_last_8(row + (g * 32 + lane) * 8, f);
            #pragma unroll
            for (int e = 0; e < 8; e++) acc[g * 8 + e] += f[e];
            rs += ((f[0] + f[1]) + (f[2] + f[3])) + ((f[4] + f[5]) + (f[6] + f[7]));
        }
        #pragma unroll
        for (int off = 16; off > 0; off >>= 1)
            rs += __shfl_down_sync(0xffffffffu, rs, off);
        if (lane == 0) d_S2[a * 256 + c] = rs;
    }

    #pragma unroll
    for (int g = 0; g < 2; g++) {
        float4* dst = (float4*)&sS0[wid][(g * 32 + lane) * 8];
        dst[0] = make_float4(acc[g * 8 + 0], acc[g * 8 + 1], acc[g * 8 + 2], acc[g * 8 + 3]);
        dst[1] = make_float4(acc[g * 8 + 4], acc[g * 8 + 5], acc[g * 8 + 6], acc[g * 8 + 7]);
    }
    __syncthreads();

    float s0 = 0.f, s1 = 0.f;
    #pragma unroll
    for (int w = 0; w < 8; w++) {
        s0 += sS0[w][tid];
        s1 += sS0[w][tid + 256];
    }
    d_S0p[half * 131072 + c * 512 + tid]       = s0;
    d_S0p[half * 131072 + c * 512 + tid + 256] = s1;
}

// ---------------------------------------------------------------------------
// K4a: msg01, colsum, msg12. grid=256 (c), block=256.
__global__ void K4a_messages() {
    const int c    = blockIdx.x;
    const int t    = threadIdx.x;
    const int lane = t & 31;
    const int wid  = t >> 5;
    __shared__ float sw[8];
    __shared__ float sbc;

    const float v0  = d_s0a[(4 * t + 0) * 256 + c];
    const float v1  = d_s0a[(4 * t + 1) * 256 + c];
    const float v2  = d_s0a[(4 * t + 2) * 256 + c];
    const float v3  = d_s0a[(4 * t + 3) * 256 + c];
    const float2 p0 = *(const float2*)&d_S0p[c * 512 + 2 * t];
    const float2 p1 = *(const float2*)&d_S0p[131072 + c * 512 + 2 * t];

    const float m01 = (v0 + v1) + (v2 + v3);
    d_msg01[t * 256 + c] = m01;

    float r = m01;
    #pragma unroll
    for (int o = 16; o > 0; o >>= 1) r += __shfl_down_sync(0xffffffffu, r, o);
    if (lane == 0) sw[wid] = r;
    __syncthreads();
    if (t == 0) {
        float s = 0.f;
        #pragma unroll
        for (int w = 0; w < 8; w++) s += sw[w];
        sbc = s;
    }
    __syncthreads();
    const float colsum = sbc;

    const float m12 = (p0.x + p1.x + colsum) + (p0.y + p1.y + colsum);
    d_msg12[c * 256 + t] = m12;
}

// ---------------------------------------------------------------------------
// KC: single pass over theta2: out2 = t2 + msg12[c,b]; directly emit
// R[c,b] = rowsum + 511*msg12. Streaming loads (.cs) and policy evict_first
// stores so protected t1 lines in L2 survive this kernel.
__global__ void KC_t2(const float* __restrict__ t2, float* __restrict__ out2) {
    const int r    = blockIdx.x * 8 + (threadIdx.x >> 5);   // r = c*256 + b
    const int lane = threadIdx.x & 31;
    const float m = d_msg12[r];

    unsigned long long pol;
    asm volatile("createpolicy.fractional.L2::evict_first.b64 %0, 1.0;" : "=l"(pol));

    const float4* row  = (const float4*)(t2   + (size_t)r * 512);
    float4*       orow = (float4*)      (out2 + (size_t)r * 512);
    float s = 0.f;
    #pragma unroll
    for (int ch = 0; ch < 4; ch++) {
        float4 v = __ldcs(row + ch * 32 + lane);
        s += (v.x + v.y) + (v.z + v.w);
        v.x += m; v.y += m; v.z += m; v.w += m;
        stg_evict_first(orow + ch * 32 + lane, v, pol);
    }
    #pragma unroll
    for (int off = 16; off > 0; off >>= 1)
        s += __shfl_down_sync(0xffffffffu, s, off);
    if (lane == 0) d_R[r] = s + 511.f * m;
}

// ---------------------------------------------------------------------------
// K4b: S21 from R, then Q. grid=256 (c), block=256 (t).
__global__ void K4b_messages() {
    const int c    = blockIdx.x;
    const int t    = threadIdx.x;
    const int lane = t & 31;
    const int wid  = t >> 5;
    __shared__ float sw[8];
    __shared__ float sbc;

    const float Rv  = d_R[c * 256 + t];
    const float s2  = d_S2[t * 256 + c];
    const float m01 = d_msg01[t * 256 + c];

    float r = Rv;
    #pragma unroll
    for (int o = 16; o > 0; o >>= 1) r += __shfl_down_sync(0xffffffffu, r, o);
    if (lane == 0) sw[wid] = r;
    __syncthreads();
    if (t == 0) {
        float s = 0.f;
        #pragma unroll
        for (int w = 0; w < 8; w++) s += sw[w];
        sbc = 2.f * s;
    }
    __syncthreads();

    d_Q[t * 256 + c] = s2 + 511.f * m01 + sbc;
}

// ---------------------------------------------------------------------------
// KE: outputs for theta1 and theta0.
//   [0, 32768)      : theta1 + msg01[a,c] + R[c, j>>1]  -- FIRST, c-DESCENDING
//                     (t1 protected in L2 by KA2's evict_last reads)
//   [32768, 98304)  : theta0 + Q[j>>2, c]
__global__ void KE_outputs(const float* __restrict__ t0,
                           const float* __restrict__ t1,
                           float* __restrict__ out) {
    const unsigned bb = blockIdx.x;

    if (bb < 32768u) {
        const int cp = 127 - (int)(bb >> 8);
        const int a  = (int)(bb & 255u);
        const int idx4 = a * 32768 + cp * 256 + threadIdx.x;
        const int i = idx4 << 2;
        const int j = i & 511;
        const int c = (i >> 9) & 255;
        const float m = d_msg01[a * 256 + c];
        const float2 rr = *(const float2*)&d_R[c * 256 + (j >> 1)];
        float4 v = __ldcs((const float4*)t1 + idx4);   // L2 hit if carry held
        v.x += m + rr.x; v.y += m + rr.x;
        v.z += m + rr.y; v.w += m + rr.y;
        __stcs((float4*)(out + N0) + idx4, v);
        return;
    }

    {
        const int idx4 = (bb - 32768u) * 256 + threadIdx.x;
        const int i = idx4 << 2;
        const int c = i & 255;
        const int j = (i >> 8) & 1023;
        float4 v = __ldcs((const float4*)t0 + idx4);
        float4 q = ((const float4*)d_Q)[((j >> 2) << 6) + (c >> 2)];
        v.x += q.x; v.y += q.y; v.z += q.z; v.w += q.w;
        __stcs((float4*)out + idx4, v);
    }
}

// ---------------------------------------------------------------------------
extern "C" void kernel_launch(void* const* d_in, const int* in_sizes, int n_in,
                              void* d_out, int out_size) {
    const float* t0 = (const float*)d_in[0];
    const float* t1 = (const float*)d_in[1];
    const float* t2 = (const float*)d_in[2];
    float* out = (float*)d_out;

    KA2_reduce<<<1536, 256>>>(t0, t1);
    K4a_messages<<<256, 256>>>();
    KC_t2<<<8192, 256>>>(t2, out + N0 + N1);
    K4b_messages<<<256, 256>>>();
    KE_outputs<<<98304, 256>>>(t0, t1, out);
}